// round 9
// baseline (speedup 1.0000x reference)
#include <cuda_runtime.h>
#include <cuda_bf16.h>
#include <cstdint>

// Problem dims
#define BB   256
#define TT   512
#define EMB  128
#define HID  256
#define NCLS 32000

#define NBLK   148       // persistent grid, 1 block/SM
#define NCHUNK 500       // 32000 / 64
#define WPITCH 272       // bytes per Wf8 smem row (17x16B, conflict-free ldmatrix)
#define WFBUF  (64 * WPITCH)   // 17408 B per fp8 W buffer

// Dynamic smem:
//   [0,      65536) : A image — H e4m3 fragments [m_tile(16)][ks(8)][lane(32)] uint4
//                     (phase-1 overlays Esh/Gsh/Hsh/toks here, disjoint lifetime)
//   [65536, 131072) : fp32 W stage (64 rows x 256 floats)
//   [131072,148480) : Wf8 buf0 ; [148480,165888) : Wf8 buf1
#define SMEM_A     0
#define SMEM_STAGE 65536
#define SMEM_W0    131072
#define SMEM_BYTES (131072 + 2 * WFBUF)

// phase-1 overlay offsets (within A region)
#define P1_ESH   0        // float[2][128]   (1 KB)
#define P1_GSH   1024     // float[3*2][256] (6 KB)
#define P1_HSH   7168     // float[2][256]   (2 KB)
#define P1_TOK   9216     // int[2]

#define SCL  64.0f
#define INVS (1.0f / 4096.0f)

__device__ uint4 g_h0p[16 * 8 * 32];   // 64 KB A-fragment master image
__device__ unsigned int g_bar;         // monotonic ticket barrier

// --------------------------- helpers ---------------------------------------
__device__ __forceinline__ uint32_t pack_e4m3(float f0, float f1, float f2, float f3)
{
    uint32_t r;
    asm("{\n\t.reg .b16 lo, hi;\n\t"
        "cvt.rn.satfinite.e4m3x2.f32 lo, %2, %1;\n\t"
        "cvt.rn.satfinite.e4m3x2.f32 hi, %4, %3;\n\t"
        "mov.b32 %0, {lo, hi};\n\t}"
        : "=r"(r) : "f"(f0), "f"(f1), "f"(f2), "f"(f3));
    return r;
}

__device__ __forceinline__ void mma_e4m3(float c[4], uint32_t a0, uint32_t a1,
                                         uint32_t a2, uint32_t a3,
                                         uint32_t b0, uint32_t b1)
{
    asm volatile(
        "mma.sync.aligned.m16n8k32.row.col.f32.e4m3.e4m3.f32 "
        "{%0,%1,%2,%3}, {%4,%5,%6,%7}, {%8,%9}, {%0,%1,%2,%3};"
        : "+f"(c[0]), "+f"(c[1]), "+f"(c[2]), "+f"(c[3])
        : "r"(a0), "r"(a1), "r"(a2), "r"(a3), "r"(b0), "r"(b1));
}

__device__ __forceinline__ void ldsm_x4(uint32_t& r0, uint32_t& r1,
                                        uint32_t& r2, uint32_t& r3, uint32_t saddr)
{
    asm volatile("ldmatrix.sync.aligned.m8n8.x4.shared.b16 {%0,%1,%2,%3}, [%4];"
                 : "=r"(r0), "=r"(r1), "=r"(r2), "=r"(r3) : "r"(saddr));
}

__device__ __forceinline__ void cp_async16(uint32_t saddr, const void* gaddr)
{
    asm volatile("cp.async.cg.shared.global [%0], [%1], 16;"
                 :: "r"(saddr), "l"(gaddr));
}

// ---------------------------------------------------------------------------
__global__ void __launch_bounds__(1024) fused_kernel(
    const int* __restrict__ X, const float* __restrict__ C_table,
    const float* __restrict__ U_i, const float* __restrict__ b_i,
    const float* __restrict__ U_c, const float* __restrict__ b_c,
    const float* __restrict__ U_o, const float* __restrict__ b_o,
    const float* __restrict__ W, const float* __restrict__ b_out,
    float* __restrict__ out)
{
    extern __shared__ char smem[];
    const int tid = threadIdx.x;
    const int bid = blockIdx.x;
    const uint32_t smem_base = (uint32_t)__cvta_generic_to_shared(smem);
    const uint32_t stage_base = smem_base + SMEM_STAGE;

    // ------ Issue chunk-0 W cp.async immediately (lands during phase 1) ---
    {
        const char* Wsrc = reinterpret_cast<const char*>(W + (size_t)bid * 64 * HID);
#pragma unroll
        for (int j = 0; j < 4; j++) {
            int idx = tid + 1024 * j;      // 0..4095 x 16B = 64KB
            cp_async16(stage_base + (uint32_t)idx * 16u, Wsrc + idx * 16);
        }
        asm volatile("cp.async.commit_group;");   // group: W0
    }

    // ===================== Phase 1: layer-0 LSTM (128 blocks x 2 rows) ====
    const bool act = (bid < 128);
    {
        float* Esh = reinterpret_cast<float*>(smem + P1_ESH);
        float* Gsh = reinterpret_cast<float*>(smem + P1_GSH);
        float* Hsh = reinterpret_cast<float*>(smem + P1_HSH);
        int*   tok = reinterpret_cast<int*>(smem + P1_TOK);

        if (act && tid < 2) tok[tid] = X[(bid * 2 + tid) * TT + (TT - 1)];
        __syncthreads();
        if (act && tid < 256) {
            int r = tid >> 7, e = tid & 127;
            Esh[r * 128 + e] = C_table[tok[r] * EMB + e];
        }
        __syncthreads();

        if (act && tid < 384) {
            const int r    = tid / 192;        // 0..1
            const int rem  = tid % 192;
            const int gate = rem >> 6;         // 0..2 (warp-uniform)
            const int hq   = rem & 63;         // h quad
            const float* Ug = (gate == 0) ? U_i : ((gate == 1) ? U_c : U_o);
            const float4* Ug4 = reinterpret_cast<const float4*>(Ug + 4 * hq);
            const float* Er = Esh + r * 128;

            float4 acc = make_float4(0.f, 0.f, 0.f, 0.f);
#pragma unroll 8
            for (int e = 0; e < EMB; e++) {
                float4 u = Ug4[e * (HID / 4)];
                float ev = Er[e];
                acc.x = fmaf(ev, u.x, acc.x);
                acc.y = fmaf(ev, u.y, acc.y);
                acc.z = fmaf(ev, u.z, acc.z);
                acc.w = fmaf(ev, u.w, acc.w);
            }
            reinterpret_cast<float4*>(Gsh)[(gate * 2 + r) * 64 + hq] = acc;
        }
        __syncthreads();

        if (act && tid < 512) {
            int r = tid >> 8, h = tid & 255;
            float ai = Gsh[(0 * 2 + r) * 256 + h] + b_i[h];
            float ac = Gsh[(1 * 2 + r) * 256 + h] + b_c[h];
            float ao = Gsh[(2 * 2 + r) * 256 + h] + b_o[h];
            float i0 = 1.f / (1.f + expf(-ai));
            float g0 = tanhf(ac);
            float o0 = 1.f / (1.f + expf(-ao));
            Hsh[r * 256 + h] = o0 * tanhf(i0 * g0);
        }
        __syncthreads();

        if (act && tid < 128) {
            uint32_t* Hw = reinterpret_cast<uint32_t*>(g_h0p);
            int r  = tid >> 6;
            int q  = tid & 63;
            int k0 = q * 4;
            int gr = bid * 2 + r;
            int m_tile = gr >> 4;
            int local  = gr & 15;
            int g      = local & 7;
            int comp_r = local >> 3;
            int ks     = q >> 3;
            int tg     = q & 3;
            int comp_k = ((q >> 2) & 1) << 1;
            int lane   = g * 4 + tg;
            uint32_t v = pack_e4m3(Hsh[r * 256 + k0] * SCL, Hsh[r * 256 + k0 + 1] * SCL,
                                   Hsh[r * 256 + k0 + 2] * SCL, Hsh[r * 256 + k0 + 3] * SCL);
            Hw[(((m_tile * 8 + ks) * 32 + lane) << 2) + (comp_r + comp_k)] = v;
        }
        __syncthreads();
    }

    // ===================== Global barrier (release/acquire) ===============
    __threadfence();
    if (tid == 0) {
        unsigned int t = atomicAdd(&g_bar, 1u);
        unsigned int target = (t / NBLK + 1u) * NBLK;
        while (*((volatile unsigned int*)&g_bar) < target) { __nanosleep(64); }
    }
    __syncthreads();
    __threadfence();

    // ------ Pull A image into smem (overwrites phase-1 overlay) -----------
#pragma unroll
    for (int j = 0; j < 4; j++) {
        int idx = tid + 1024 * j;
        cp_async16(smem_base + SMEM_A + (uint32_t)idx * 16u,
                   reinterpret_cast<const char*>(g_h0p) + idx * 16);
    }
    asm volatile("cp.async.commit_group;");       // group: A (W0 older)

    const int nch = (NCHUNK - bid + NBLK - 1) / NBLK;   // 3 or 4 chunks

    // ===================== Phase 2: logits = H @ W^T + b ==================
    const int wid  = tid >> 5;
    const int lane = tid & 31;
    const int mt   = wid & 15;         // m-tile
    const int nh   = wid >> 4;         // n-half (0/1)
    const int g  = lane >> 2;
    const int tg = lane & 3;

    const int rowIn16 = ((lane >> 4) << 3) + (lane & 7);
    const int halfoff = ((lane >> 3) & 1) * 16;
    const uint32_t lmOff  = (uint32_t)(nh * 32 * WPITCH + rowIn16 * WPITCH + halfoff);
    const uint32_t stsOff = (uint32_t)((tid >> 4) * WPITCH + (tid & 15) * 16);
    const int stageIdx = (tid >> 4) * 64 + (tid & 15) * 4;   // float4 index

#pragma unroll 1
    for (int i = 0; i < nch; i++) {
        const int buf = i & 1;
        const uint32_t wbase = smem_base + SMEM_W0 + (uint32_t)buf * WFBUF;

        // Wait for W_i (and A on first iter), then pack stage -> Wf8[buf]
        if (i == 0) {
            asm volatile("cp.async.wait_group 1;");   // W0 done (A may fly)
        } else {
            asm volatile("cp.async.wait_group 0;");   // W_i done
        }
        {
            const float4* st4 = reinterpret_cast<const float4*>(smem + SMEM_STAGE);
            float4 v0 = st4[stageIdx + 0];
            float4 v1 = st4[stageIdx + 1];
            float4 v2 = st4[stageIdx + 2];
            float4 v3 = st4[stageIdx + 3];
            uint4 v;
            v.x = pack_e4m3(v0.x * SCL, v0.y * SCL, v0.z * SCL, v0.w * SCL);
            v.y = pack_e4m3(v1.x * SCL, v1.y * SCL, v1.z * SCL, v1.w * SCL);
            v.z = pack_e4m3(v2.x * SCL, v2.y * SCL, v2.z * SCL, v2.w * SCL);
            v.w = pack_e4m3(v3.x * SCL, v3.y * SCL, v3.z * SCL, v3.w * SCL);
            asm volatile("st.shared.v4.b32 [%0], {%1,%2,%3,%4};"
                         :: "r"(wbase + stsOff), "r"(v.x), "r"(v.y), "r"(v.z), "r"(v.w));
        }

        // Issue W_{i+1} into stage (each thread overwrites only bytes it read)
        if (i + 1 < nch) {
            const char* Wsrc = reinterpret_cast<const char*>(
                W + (size_t)(bid + NBLK * (i + 1)) * 64 * HID);
#pragma unroll
            for (int j = 0; j < 4; j++) {
                int idx = tid + 1024 * j;
                cp_async16(stage_base + (uint32_t)idx * 16u, Wsrc + idx * 16);
            }
            asm volatile("cp.async.commit_group;");
        }

        if (i == 0) asm volatile("cp.async.wait_group %0;" :: "n"(1));  // A done
        __syncthreads();

        float c[4][4];
#pragma unroll
        for (int nf = 0; nf < 4; nf++)
#pragma unroll
            for (int q = 0; q < 4; q++) c[nf][q] = 0.f;

        const uint32_t WB = wbase + lmOff;
#pragma unroll
        for (int ks = 0; ks < 8; ks++) {
            uint4 va = *reinterpret_cast<const uint4*>(
                smem + SMEM_A + (size_t)(mt * 8 + ks) * 512 + lane * 16);
            const uint32_t kb = (uint32_t)(ks * 32);
#pragma unroll
            for (int nfp = 0; nfp < 2; nfp++) {
                uint32_t b0r, b1r, b2r, b3r;
                ldsm_x4(b0r, b1r, b2r, b3r, WB + (uint32_t)(nfp * 16 * WPITCH) + kb);
                mma_e4m3(c[2 * nfp],     va.x, va.y, va.z, va.w, b0r, b1r);
                mma_e4m3(c[2 * nfp + 1], va.x, va.y, va.z, va.w, b2r, b3r);
            }
        }

        const int n_base = (bid + NBLK * i) * 64 + nh * 32;
        const int r0 = mt * 16 + g;
#pragma unroll
        for (int nf = 0; nf < 4; nf++) {
            const int n = n_base + nf * 8 + tg * 2;
            const float2 bo = *reinterpret_cast<const float2*>(b_out + n);
            float2 v0 = make_float2(fmaf(c[nf][0], INVS, bo.x),
                                    fmaf(c[nf][1], INVS, bo.y));
            float2 v1 = make_float2(fmaf(c[nf][2], INVS, bo.x),
                                    fmaf(c[nf][3], INVS, bo.y));
            *reinterpret_cast<float2*>(out + (size_t)(r0    ) * NCLS + n) = v0;
            *reinterpret_cast<float2*>(out + (size_t)(r0 + 8) * NCLS + n) = v1;
        }
        // One sync per iteration + buffer alternation keeps smem reuse safe.
    }
}

// ---------------------------------------------------------------------------
extern "C" void kernel_launch(void* const* d_in, const int* in_sizes, int n_in,
                              void* d_out, int out_size)
{
    const int*   X       = (const int*)  d_in[0];
    const float* C_table = (const float*)d_in[1];
    const float* U_i     = (const float*)d_in[2];
    const float* b_i     = (const float*)d_in[4];
    const float* U_c     = (const float*)d_in[8];
    const float* b_c     = (const float*)d_in[10];
    const float* U_o     = (const float*)d_in[11];
    const float* b_o     = (const float*)d_in[13];
    const float* W_w     = (const float*)d_in[26];
    const float* b_out   = (const float*)d_in[27];
    float* out = (float*)d_out;

    cudaFuncSetAttribute(fused_kernel,
                         cudaFuncAttributeMaxDynamicSharedMemorySize, SMEM_BYTES);

    fused_kernel<<<NBLK, 1024, SMEM_BYTES>>>(X, C_table, U_i, b_i, U_c, b_c,
                                             U_o, b_o, W_w, b_out, out);
}

// round 10
// speedup vs baseline: 1.2099x; 1.2099x over previous
#include <cuda_runtime.h>
#include <cuda_bf16.h>
#include <cstdint>

// Problem dims
#define BB   256
#define TT   512
#define EMB  128
#define HID  256
#define NCLS 32000

#define NBLK   148       // persistent grid, 1 block/SM
#define NCHUNK 1000      // 32000 / 32
#define WPITCH 272       // bytes per Wf8 smem row (17x16B -> conflict-free ldmatrix)
#define WBUF   (32 * WPITCH)   // 8704 B per chunk buffer

// Dynamic smem:
//   [0,     65536) : A image — H e4m3 fragments [m_tile(16)][ks(8)][lane(32)] uint4
//   [65536, +WBUF) : Wf8 buf0 ; [+WBUF, +2*WBUF) : Wf8 buf1
//   phase-1 overlays Esh/Gsh/Hsh/toks on the Wf8 region (12.1 KB < 17.4 KB)
#define SMEM_A     0
#define SMEM_W0    65536
#define SMEM_BYTES (65536 + 2 * WBUF)

// phase-1 overlay offsets (within Wf8 region, i.e. +SMEM_W0)
#define P1_ESH 0        // float[8][128]  4 KB
#define P1_GSH 4096     // float[3][8][64] 6 KB
#define P1_HSH 10240    // float[8][64]   2 KB
#define P1_TOK 12288    // int[8]

#define SCL  64.0f                 // quantization scale for A and W
#define INVS (1.0f / 4096.0f)      // 1/(SCL*SCL)

__device__ uint4 g_h0p[16 * 8 * 32];   // 64 KB A-fragment master image
__device__ unsigned int g_bar;         // monotonic ticket barrier

// --------------------------- helpers ---------------------------------------
__device__ __forceinline__ uint32_t pack_e4m3(float f0, float f1, float f2, float f3)
{
    uint32_t r;
    asm("{\n\t.reg .b16 lo, hi;\n\t"
        "cvt.rn.satfinite.e4m3x2.f32 lo, %2, %1;\n\t"
        "cvt.rn.satfinite.e4m3x2.f32 hi, %4, %3;\n\t"
        "mov.b32 %0, {lo, hi};\n\t}"
        : "=r"(r) : "f"(f0), "f"(f1), "f"(f2), "f"(f3));
    return r;
}

__device__ __forceinline__ void mma_e4m3(float c[4], uint32_t a0, uint32_t a1,
                                         uint32_t a2, uint32_t a3,
                                         uint32_t b0, uint32_t b1)
{
    asm volatile(
        "mma.sync.aligned.m16n8k32.row.col.f32.e4m3.e4m3.f32 "
        "{%0,%1,%2,%3}, {%4,%5,%6,%7}, {%8,%9}, {%0,%1,%2,%3};"
        : "+f"(c[0]), "+f"(c[1]), "+f"(c[2]), "+f"(c[3])
        : "r"(a0), "r"(a1), "r"(a2), "r"(a3), "r"(b0), "r"(b1));
}

__device__ __forceinline__ void ldsm_x4(uint32_t& r0, uint32_t& r1,
                                        uint32_t& r2, uint32_t& r3, uint32_t saddr)
{
    asm volatile("ldmatrix.sync.aligned.m8n8.x4.shared.b16 {%0,%1,%2,%3}, [%4];"
                 : "=r"(r0), "=r"(r1), "=r"(r2), "=r"(r3) : "r"(saddr));
}

__device__ __forceinline__ void cp_async16(uint32_t saddr, const void* gaddr)
{
    asm volatile("cp.async.cg.shared.global [%0], [%1], 16;"
                 :: "r"(saddr), "l"(gaddr));
}

// ---------------------------------------------------------------------------
__global__ void __launch_bounds__(512) fused_kernel(
    const int* __restrict__ X, const float* __restrict__ C_table,
    const float* __restrict__ U_i, const float* __restrict__ b_i,
    const float* __restrict__ U_c, const float* __restrict__ b_c,
    const float* __restrict__ U_o, const float* __restrict__ b_o,
    const float* __restrict__ W, const float* __restrict__ b_out,
    float* __restrict__ out)
{
    extern __shared__ char smem[];
    const int tid = threadIdx.x;
    const int bid = blockIdx.x;
    const uint32_t smem_base = (uint32_t)__cvta_generic_to_shared(smem);

    // ===================== Phase 1: layer-0 LSTM, h-sliced ================
    // 128 tiles: tile = (8 batch rows, 64-h slice). Block bid<128 does tile bid.
    // U traffic per block: 3 x 128 x 64 x 4B = 96 KB (12 MB chip-wide).
    const bool act = (bid < 128);
    const int b0 = (bid & 31) * 8;       // batch-row base
    const int hb = (bid >> 5) * 64;      // h-slice base
    {
        float* Esh = reinterpret_cast<float*>(smem + SMEM_W0 + P1_ESH);
        float* Gsh = reinterpret_cast<float*>(smem + SMEM_W0 + P1_GSH);
        float* Hsh = reinterpret_cast<float*>(smem + SMEM_W0 + P1_HSH);
        int*   tok = reinterpret_cast<int*>(smem + SMEM_W0 + P1_TOK);

        if (act && tid < 8) tok[tid] = X[(b0 + tid) * TT + (TT - 1)];
        __syncthreads();
        if (act && tid < 256) {
            int idx0 = tid * 4;
            int r = idx0 >> 7;           // wait: 256 thr x 4 floats = 1024 = 8x128
            int e = idx0 & 127;
            float4 v = make_float4(C_table[tok[r] * EMB + e],
                                   C_table[tok[r] * EMB + e + 1],
                                   C_table[tok[r] * EMB + e + 2],
                                   C_table[tok[r] * EMB + e + 3]);
            *reinterpret_cast<float4*>(Esh + r * 128 + e) = v;
        }
        __syncthreads();

        if (act && tid < 384) {
            const int gate = tid >> 7;           // 0..2 (warp-uniform)
            const int rem  = tid & 127;
            const int r    = rem >> 4;           // 0..7
            const int hq   = rem & 15;           // 16 quads -> 64 h
            const float* Ug = (gate == 0) ? U_i : ((gate == 1) ? U_c : U_o);
            const float4* Ug4 = reinterpret_cast<const float4*>(Ug + hb + 4 * hq);
            const float* Er = Esh + r * 128;

            float4 acc = make_float4(0.f, 0.f, 0.f, 0.f);
#pragma unroll 8
            for (int e = 0; e < EMB; e++) {
                float4 u = Ug4[e * (HID / 4)];
                float ev = Er[e];
                acc.x = fmaf(ev, u.x, acc.x);
                acc.y = fmaf(ev, u.y, acc.y);
                acc.z = fmaf(ev, u.z, acc.z);
                acc.w = fmaf(ev, u.w, acc.w);
            }
            reinterpret_cast<float4*>(Gsh)[(gate * 8 + r) * 16 + hq] = acc;
        }
        __syncthreads();

        if (act) {                                // 512 thr: (r, h_local)
            int r = tid >> 6, hl = tid & 63;
            int h = hb + hl;
            float ai = Gsh[(0 * 8 + r) * 64 + hl] + b_i[h];
            float ac = Gsh[(1 * 8 + r) * 64 + hl] + b_c[h];
            float ao = Gsh[(2 * 8 + r) * 64 + hl] + b_o[h];
            float i0 = 1.f / (1.f + expf(-ai));
            float g0 = tanhf(ac);
            float o0 = 1.f / (1.f + expf(-ao));
            Hsh[r * 64 + hl] = o0 * tanhf(i0 * g0);
        }
        __syncthreads();

        if (act && tid < 128) {
            // Pack 4 consecutive h into one e4m3 word, fragment layout.
            uint32_t* Hw = reinterpret_cast<uint32_t*>(g_h0p);
            int r  = tid >> 4;                   // 0..7
            int ql = tid & 15;                   // local quad
            int qg = (hb >> 2) + ql;             // global quad 0..63
            int gr = b0 + r;
            int m_tile = gr >> 4;
            int local  = gr & 15;
            int g      = local & 7;
            int comp_r = local >> 3;
            int ks     = qg >> 3;
            int tg     = qg & 3;
            int comp_k = ((qg >> 2) & 1) << 1;
            int lane   = g * 4 + tg;
            int k0l    = ql * 4;
            uint32_t v = pack_e4m3(Hsh[r * 64 + k0l] * SCL, Hsh[r * 64 + k0l + 1] * SCL,
                                   Hsh[r * 64 + k0l + 2] * SCL, Hsh[r * 64 + k0l + 3] * SCL);
            Hw[(((m_tile * 8 + ks) * 32 + lane) << 2) + (comp_r + comp_k)] = v;
        }
        __syncthreads();   // Wf8 region free for reuse
    }

    const int nch = (NCHUNK - bid + NBLK - 1) / NBLK;   // 6 or 7 chunks

    // ------ Prefetch chunk-0 W into registers (covers barrier wait) -------
    float4 wreg[4];
    {
        const float4* W4 = reinterpret_cast<const float4*>(
            W + (size_t)(bid * 32 + (tid >> 4)) * HID + (tid & 15) * 16);
#pragma unroll
        for (int j = 0; j < 4; j++) wreg[j] = W4[j];
    }

    // ===================== Global barrier (release/acquire) ===============
    __threadfence();
    if (tid == 0) {
        unsigned int t = atomicAdd(&g_bar, 1u);
        unsigned int target = (t / NBLK + 1u) * NBLK;
        while (*((volatile unsigned int*)&g_bar) < target) { __nanosleep(64); }
    }
    __syncthreads();
    __threadfence();

    // ------ Pull A image into smem (linear cp.async, 128B/thread) ---------
#pragma unroll
    for (int j = 0; j < 8; j++) {
        int idx = tid + 512 * j;       // 0..4095 x 16B = 64KB
        cp_async16(smem_base + SMEM_A + (uint32_t)idx * 16u,
                   reinterpret_cast<const char*>(g_h0p) + idx * 16);
    }
    asm volatile("cp.async.commit_group;");

    // ===================== Phase 2: logits = H @ W^T + b ==================
    const int warp = tid >> 5;         // m-tile 0..15
    const int lane = tid & 31;
    const int g  = lane >> 2;
    const int tg = lane & 3;

    const int rowIn16 = ((lane >> 4) << 3) + (lane & 7);
    const int halfoff = ((lane >> 3) & 1) * 16;
    const uint32_t lmOff = (uint32_t)(rowIn16 * WPITCH + halfoff);
    const uint32_t stsOff = (uint32_t)((tid >> 4) * WPITCH + (tid & 15) * 16);

#pragma unroll 1
    for (int i = 0; i < nch; i++) {
        const int buf = i & 1;
        const uint32_t wbase = smem_base + SMEM_W0 + (uint32_t)buf * WBUF;
        const int n_base = (bid + NBLK * i) * 32;

        // Prefetch b_out (hides L2 latency under pack+sync+mma)
        float2 bo[4];
#pragma unroll
        for (int nf = 0; nf < 4; nf++)
            bo[nf] = *reinterpret_cast<const float2*>(b_out + n_base + nf * 8 + tg * 2);

        // Convert prefetched W_i regs -> e4m3 Wf8[buf]
        {
            uint4 v;
            v.x = pack_e4m3(wreg[0].x * SCL, wreg[0].y * SCL, wreg[0].z * SCL, wreg[0].w * SCL);
            v.y = pack_e4m3(wreg[1].x * SCL, wreg[1].y * SCL, wreg[1].z * SCL, wreg[1].w * SCL);
            v.z = pack_e4m3(wreg[2].x * SCL, wreg[2].y * SCL, wreg[2].z * SCL, wreg[2].w * SCL);
            v.w = pack_e4m3(wreg[3].x * SCL, wreg[3].y * SCL, wreg[3].z * SCL, wreg[3].w * SCL);
            asm volatile("st.shared.v4.b32 [%0], {%1,%2,%3,%4};"
                         :: "r"(wbase + stsOff), "r"(v.x), "r"(v.y), "r"(v.z), "r"(v.w));
        }

        // Prefetch W_{i+1} into registers (overlaps this chunk's MMA loop)
        if (i + 1 < nch) {
            const float4* W4 = reinterpret_cast<const float4*>(
                W + (size_t)((bid + NBLK * (i + 1)) * 32 + (tid >> 4)) * HID +
                (tid & 15) * 16);
#pragma unroll
            for (int j = 0; j < 4; j++) wreg[j] = W4[j];
        }

        if (i == 0) asm volatile("cp.async.wait_group 0;");   // A image ready
        __syncthreads();

        float c[4][4];
#pragma unroll
        for (int nf = 0; nf < 4; nf++)
#pragma unroll
            for (int q = 0; q < 4; q++) c[nf][q] = 0.f;

        const uint32_t WB = wbase + lmOff;
#pragma unroll
        for (int ks = 0; ks < 8; ks++) {
            uint4 va = *reinterpret_cast<const uint4*>(
                smem + SMEM_A + (size_t)(warp * 8 + ks) * 512 + lane * 16);
            const uint32_t kb = (uint32_t)(ks * 32);
#pragma unroll
            for (int nfp = 0; nfp < 2; nfp++) {
                uint32_t b0r, b1r, b2r, b3r;
                ldsm_x4(b0r, b1r, b2r, b3r, WB + (uint32_t)(nfp * 16 * WPITCH) + kb);
                mma_e4m3(c[2 * nfp],     va.x, va.y, va.z, va.w, b0r, b1r);
                mma_e4m3(c[2 * nfp + 1], va.x, va.y, va.z, va.w, b2r, b3r);
            }
        }

        const int r0 = warp * 16 + g;
#pragma unroll
        for (int nf = 0; nf < 4; nf++) {
            const int n = n_base + nf * 8 + tg * 2;
            float2 v0 = make_float2(fmaf(c[nf][0], INVS, bo[nf].x),
                                    fmaf(c[nf][1], INVS, bo[nf].y));
            float2 v1 = make_float2(fmaf(c[nf][2], INVS, bo[nf].x),
                                    fmaf(c[nf][3], INVS, bo[nf].y));
            *reinterpret_cast<float2*>(out + (size_t)(r0    ) * NCLS + n) = v0;
            *reinterpret_cast<float2*>(out + (size_t)(r0 + 8) * NCLS + n) = v1;
        }
        // One sync per iteration + buffer alternation keeps smem reuse safe.
    }
}

// ---------------------------------------------------------------------------
extern "C" void kernel_launch(void* const* d_in, const int* in_sizes, int n_in,
                              void* d_out, int out_size)
{
    const int*   X       = (const int*)  d_in[0];
    const float* C_table = (const float*)d_in[1];
    const float* U_i     = (const float*)d_in[2];
    const float* b_i     = (const float*)d_in[4];
    const float* U_c     = (const float*)d_in[8];
    const float* b_c     = (const float*)d_in[10];
    const float* U_o     = (const float*)d_in[11];
    const float* b_o     = (const float*)d_in[13];
    const float* W_w     = (const float*)d_in[26];
    const float* b_out   = (const float*)d_in[27];
    float* out = (float*)d_out;

    cudaFuncSetAttribute(fused_kernel,
                         cudaFuncAttributeMaxDynamicSharedMemorySize, SMEM_BYTES);

    fused_kernel<<<NBLK, 512, SMEM_BYTES>>>(X, C_table, U_i, b_i, U_c, b_c,
                                            U_o, b_o, W_w, b_out, out);
}